// round 14
// baseline (speedup 1.0000x reference)
#include <cuda_runtime.h>
#include <math.h>
#include <stdint.h>

#define B_SZ 512
#define NTOK 49
#define CDIM 256
#define HH 8
#define DHD 32
#define RB 8
#define NRF 32
#define NWIN 64
#define DCC 64
#define TCC 384
#define ROWS (B_SZ*NTOK)          /* 25088 */
#define SCALEF 0.17677669529663687f
#define PLANE 100352              /* 3136*32 */
#define INVPLANE (1.f/100352.f)

// ---------------- scratch (device globals; no allocation allowed) ----------------
__device__ float g_qkv[ROWS*768];
__device__ float g_refqk[256*512];
__device__ float g_refq[RB*HH*NRF*DHD];
__device__ float g_refv[RB*HH*NRF*DHD];
__device__ float g_attn[RB*HH*NWIN*NTOK*NRF];   // 6,422,528
__device__ float g_attn2[RB*HH*NWIN*NTOK*NRF];
__device__ float g_u[RB*HH*NWIN*NTOK*NRF];
__device__ float g_u2[RB*HH*NWIN*NTOK*NRF];
__device__ float g_stats[3*RB*HH*2];
__device__ float g_s1[ROWS*CDIM];
__device__ float g_z[ROWS*CDIM];
__device__ float g_qn[ROWS*CDIM];
__device__ float g_av[ROWS*CDIM];
__device__ float g_dq[ROWS*DCC];
__device__ float g_sq[ROWS*DCC];
__device__ float g_dstok[2*ROWS*DCC];
__device__ float g_tx[ROWS*TCC];
__device__ float g_tk[ROWS*TCC];
__device__ float g_tv[ROWS*TCC];
// pre-converted tf32 weights
__device__ uint32_t g_wcvt[196608+131072+65536+65536+147456+147456];
#define WOFF_QKV   0
#define WOFF_REFQK 196608
#define WOFF_QPROJ (196608+131072)
#define WOFF_PROJ  (196608+131072+65536)
#define WOFF_GK    (196608+131072+65536+65536)
#define WOFF_GV    (196608+131072+65536+65536+147456)

// =================================================================================
// TF32 tensor-core GEMM. B pre-converted tf32. Optional dual-B via blockIdx.z.
// Optional txout: epilogue also writes C rows into txout (stride TCC) — used to
// fuse the concat's out-copy into the out-proj GEMM.
// =================================================================================
__device__ __forceinline__ uint32_t f2tf32(float f) {
    uint32_t r;
    asm("cvt.rna.tf32.f32 %0, %1;" : "=r"(r) : "f"(f));
    return r;
}

__device__ __forceinline__ void mma_tf32(float c[4],
    uint32_t a0, uint32_t a1, uint32_t a2, uint32_t a3,
    uint32_t b0, uint32_t b1)
{
    asm volatile(
        "mma.sync.aligned.m16n8k8.row.col.f32.tf32.tf32.f32 "
        "{%0,%1,%2,%3}, {%4,%5,%6,%7}, {%8,%9}, {%0,%1,%2,%3};"
        : "+f"(c[0]), "+f"(c[1]), "+f"(c[2]), "+f"(c[3])
        : "r"(a0), "r"(a1), "r"(a2), "r"(a3), "r"(b0), "r"(b1));
}

// weight pre-convert
__global__ __launch_bounds__(256) void wconv_kernel(
    const float* __restrict__ w0, int n0, int o0,
    const float* __restrict__ w1, int n1, int o1,
    const float* __restrict__ w2, int n2, int o2,
    const float* __restrict__ w3, int n3, int o3,
    const float* __restrict__ w4, int n4, int o4,
    const float* __restrict__ w5, int n5, int o5)
{
    long i = (long)blockIdx.x * 256 + threadIdx.x;
    if (i < n0) g_wcvt[o0 + i] = f2tf32(w0[i]);
    if (i < n1) g_wcvt[o1 + i] = f2tf32(w1[i]);
    if (i < n2) g_wcvt[o2 + i] = f2tf32(w2[i]);
    if (i < n3) g_wcvt[o3 + i] = f2tf32(w3[i]);
    if (i < n4) g_wcvt[o4 + i] = f2tf32(w4[i]);
    if (i < n5) g_wcvt[o5 + i] = f2tf32(w5[i]);
}

#define APITCH 24
#define BPAD 136
__global__ __launch_bounds__(256, 2) void mgemm_tf32(
    const float* __restrict__ A, const uint32_t* __restrict__ B0_,
    const float* __restrict__ bias0_, const uint32_t* __restrict__ B1_,
    const float* __restrict__ bias1_, const float* __restrict__ addp,
    int add_ld, float scale, float* __restrict__ C0_, float* __restrict__ C1_,
    float* __restrict__ txout, int M, int N, int K)
{
    const uint32_t* B = (blockIdx.z && B1_) ? B1_ : B0_;
    const float* bias = (blockIdx.z && B1_) ? bias1_ : bias0_;
    float* C = (blockIdx.z && B1_) ? C1_ : C0_;

    __shared__ __align__(16) uint32_t As[2][128][APITCH];
    __shared__ __align__(16) uint32_t Bs[2][8][BPAD];
    const int bm = blockIdx.y * 128;
    const int bn = blockIdx.x * 128;
    const int t = threadIdx.x;
    const int lane = t & 31;
    const int w = t >> 5;
    const int wm = (w >> 2) * 64;
    const int wn = (w & 3) * 32;
    const int g = lane >> 2;
    const int tig = lane & 3;

    const int a_row = t >> 1;
    const int a_k   = (t & 1) * 4;
    const int a_c   = a_k >> 2;
    const int b_k   = t >> 5;
    const int b_n   = (t & 31) * 4;

    const float* Ap = A + (long)(bm + a_row) * K + a_k;
    const uint32_t* Bp = B + (long)b_k * N + bn + b_n;
    const long bstep = (long)8 * N;

    float c[16][4];
#pragma unroll
    for (int i = 0; i < 16; i++)
#pragma unroll
        for (int j = 0; j < 4; j++) c[i][j] = 0.f;

    float4 a_reg;
    uint4 b_reg;

#define STORE_TILE(BUF)                                                  \
    do {                                                                 \
        As[BUF][a_row][0 * 2 + a_c] = f2tf32(a_reg.x);                   \
        As[BUF][a_row][1 * 2 + a_c] = f2tf32(a_reg.y);                   \
        As[BUF][a_row][2 * 2 + a_c] = f2tf32(a_reg.z);                   \
        As[BUF][a_row][3 * 2 + a_c] = f2tf32(a_reg.w);                   \
        *(uint4*)&Bs[BUF][b_k][b_n] = b_reg;                             \
    } while (0)

#define COMPUTE_TILE(BUF)                                                \
    do {                                                                 \
        uint32_t af[4][4];                                               \
        _Pragma("unroll")                                                \
        for (int mi = 0; mi < 4; mi++) {                                 \
            int m0 = wm + mi * 16 + g;                                   \
            uint2 pa = *(const uint2*)&As[BUF][m0][tig * 2];             \
            uint2 pb = *(const uint2*)&As[BUF][m0 + 8][tig * 2];         \
            af[mi][0] = pa.x;                                            \
            af[mi][1] = pb.x;                                            \
            af[mi][2] = pa.y;                                            \
            af[mi][3] = pb.y;                                            \
        }                                                                \
        uint32_t bf[4][2];                                               \
        _Pragma("unroll")                                                \
        for (int ni = 0; ni < 4; ni++) {                                 \
            int n0 = wn + ni * 8 + g;                                    \
            bf[ni][0] = Bs[BUF][tig][n0];                                \
            bf[ni][1] = Bs[BUF][tig + 4][n0];                            \
        }                                                                \
        _Pragma("unroll")                                                \
        for (int mi = 0; mi < 4; mi++)                                   \
            _Pragma("unroll")                                            \
            for (int ni = 0; ni < 4; ni++)                               \
                mma_tf32(c[mi * 4 + ni], af[mi][0], af[mi][1],           \
                         af[mi][2], af[mi][3], bf[ni][0], bf[ni][1]);    \
    } while (0)

    a_reg = *(const float4*)Ap;
    b_reg = *(const uint4*)Bp;
    STORE_TILE(0);
    __syncthreads();

    const int nk = K >> 3;               // EVEN for all call sites
    for (int kt = 0; kt < nk; kt += 2) {
        a_reg = *(const float4*)(Ap + (kt + 1) * 8);
        b_reg = *(const uint4*)(Bp + (long)(kt + 1) * bstep);
        COMPUTE_TILE(0);
        STORE_TILE(1);
        __syncthreads();
        bool more = (kt + 2) < nk;
        if (more) {
            a_reg = *(const float4*)(Ap + (kt + 2) * 8);
            b_reg = *(const uint4*)(Bp + (long)(kt + 2) * bstep);
        }
        COMPUTE_TILE(1);
        if (more) {
            STORE_TILE(0);
            __syncthreads();
        }
    }
#undef STORE_TILE
#undef COMPUTE_TILE

#pragma unroll
    for (int mi = 0; mi < 4; mi++) {
#pragma unroll
        for (int ni = 0; ni < 4; ni++) {
            int n = bn + wn + ni * 8 + tig * 2;
            float b0 = bias[n], b1 = bias[n + 1];
            int m1 = bm + wm + mi * 16 + g;
            int m2 = m1 + 8;
            float v0 = c[mi * 4 + ni][0] + b0;
            float v1 = c[mi * 4 + ni][1] + b1;
            float v2 = c[mi * 4 + ni][2] + b0;
            float v3 = c[mi * 4 + ni][3] + b1;
            if (addp) {
                const float* ar1 = addp + (long)m1 * add_ld + n;
                const float* ar2 = addp + (long)m2 * add_ld + n;
                v0 += ar1[0]; v1 += ar1[1];
                v2 += ar2[0]; v3 += ar2[1];
            }
            float2 o1 = make_float2(v0 * scale, v1 * scale);
            float2 o2 = make_float2(v2 * scale, v3 * scale);
            *(float2*)(C + (long)m1 * N + n) = o1;
            *(float2*)(C + (long)m2 * N + n) = o2;
            if (txout) {
                *(float2*)(txout + (long)m1 * TCC + n) = o1;
                *(float2*)(txout + (long)m2 * TCC + n) = o2;
            }
        }
    }
}

// ---------------- 64x64 tiled SGEMM (small GEMMs) ---------------------------------
__global__ __launch_bounds__(256) void sgemm64(
    const float* __restrict__ A, const float* __restrict__ B,
    const float* __restrict__ bias, const float* __restrict__ addp,
    int add_ld, float scale, float* __restrict__ C,
    int M, int N, int K)
{
    __shared__ __align__(16) float As[16][64];
    __shared__ __align__(16) float Bs[16][64];
    const int bm = blockIdx.y * 64;
    const int bn = blockIdx.x * 64;
    const int t  = threadIdx.x;
    const int tx = t & 15, ty = t >> 4;
    const int a_m = t >> 2, a_k = (t & 3) << 2;
    const int b_k = t >> 4, b_n = (t & 15) << 2;

    float acc[4][4];
#pragma unroll
    for (int i = 0; i < 4; i++)
#pragma unroll
        for (int j = 0; j < 4; j++) acc[i][j] = 0.f;

    const float* Aptr = A + (long)(bm + a_m) * K + a_k;
    const float* Bptr = B + (long)b_k * N + bn + b_n;

    for (int k0 = 0; k0 < K; k0 += 16) {
        float4 av = *(const float4*)(Aptr + k0);
        As[a_k + 0][a_m] = av.x;
        As[a_k + 1][a_m] = av.y;
        As[a_k + 2][a_m] = av.z;
        As[a_k + 3][a_m] = av.w;
        *(float4*)&Bs[b_k][b_n] = *(const float4*)(Bptr + (long)k0 * N);
        __syncthreads();
#pragma unroll
        for (int kk = 0; kk < 16; kk++) {
            float4 a4 = *(const float4*)&As[kk][ty << 2];
            float4 b4 = *(const float4*)&Bs[kk][tx << 2];
            acc[0][0] += a4.x * b4.x; acc[0][1] += a4.x * b4.y;
            acc[0][2] += a4.x * b4.z; acc[0][3] += a4.x * b4.w;
            acc[1][0] += a4.y * b4.x; acc[1][1] += a4.y * b4.y;
            acc[1][2] += a4.y * b4.z; acc[1][3] += a4.y * b4.w;
            acc[2][0] += a4.z * b4.x; acc[2][1] += a4.z * b4.y;
            acc[2][2] += a4.z * b4.z; acc[2][3] += a4.z * b4.w;
            acc[3][0] += a4.w * b4.x; acc[3][1] += a4.w * b4.y;
            acc[3][2] += a4.w * b4.z; acc[3][3] += a4.w * b4.w;
        }
        __syncthreads();
    }
#pragma unroll
    for (int i = 0; i < 4; i++) {
        int m = bm + (ty << 2) + i;
#pragma unroll
        for (int j = 0; j < 4; j++) {
            int n = bn + (tx << 2) + j;
            float v = acc[i][j] + bias[n];
            if (addp) v += addp[(long)m * add_ld + n];
            C[(long)m * N + n] = v * scale;
        }
    }
}

// ---------------- dual small SGEMM: z selects operand set -------------------------
__global__ __launch_bounds__(256) void sgemm64_dual(
    const float* __restrict__ A0, const float* __restrict__ B0,
    const float* __restrict__ bias0, float* __restrict__ C0,
    const float* __restrict__ A1, const float* __restrict__ B1,
    const float* __restrict__ bias1, float* __restrict__ C1,
    float scale, int M, int N, int K)
{
    const float* A = blockIdx.z ? A1 : A0;
    const float* B = blockIdx.z ? B1 : B0;
    const float* bias = blockIdx.z ? bias1 : bias0;
    float* C = blockIdx.z ? C1 : C0;

    __shared__ __align__(16) float As[16][64];
    __shared__ __align__(16) float Bs[16][64];
    const int bm = blockIdx.y * 64;
    const int bn = blockIdx.x * 64;
    const int t  = threadIdx.x;
    const int tx = t & 15, ty = t >> 4;
    const int a_m = t >> 2, a_k = (t & 3) << 2;
    const int b_k = t >> 4, b_n = (t & 15) << 2;

    float acc[4][4];
#pragma unroll
    for (int i = 0; i < 4; i++)
#pragma unroll
        for (int j = 0; j < 4; j++) acc[i][j] = 0.f;

    const float* Aptr = A + (long)(bm + a_m) * K + a_k;
    const float* Bptr = B + (long)b_k * N + bn + b_n;

    for (int k0 = 0; k0 < K; k0 += 16) {
        float4 av = *(const float4*)(Aptr + k0);
        As[a_k + 0][a_m] = av.x;
        As[a_k + 1][a_m] = av.y;
        As[a_k + 2][a_m] = av.z;
        As[a_k + 3][a_m] = av.w;
        *(float4*)&Bs[b_k][b_n] = *(const float4*)(Bptr + (long)k0 * N);
        __syncthreads();
#pragma unroll
        for (int kk = 0; kk < 16; kk++) {
            float4 a4 = *(const float4*)&As[kk][ty << 2];
            float4 b4 = *(const float4*)&Bs[kk][tx << 2];
            acc[0][0] += a4.x * b4.x; acc[0][1] += a4.x * b4.y;
            acc[0][2] += a4.x * b4.z; acc[0][3] += a4.x * b4.w;
            acc[1][0] += a4.y * b4.x; acc[1][1] += a4.y * b4.y;
            acc[1][2] += a4.y * b4.z; acc[1][3] += a4.y * b4.w;
            acc[2][0] += a4.z * b4.x; acc[2][1] += a4.z * b4.y;
            acc[2][2] += a4.z * b4.z; acc[2][3] += a4.z * b4.w;
            acc[3][0] += a4.w * b4.x; acc[3][1] += a4.w * b4.y;
            acc[3][2] += a4.w * b4.z; acc[3][3] += a4.w * b4.w;
        }
        __syncthreads();
    }
#pragma unroll
    for (int i = 0; i < 4; i++) {
        int m = bm + (ty << 2) + i;
#pragma unroll
        for (int j = 0; j < 4; j++) {
            int n = bn + (tx << 2) + j;
            C[(long)m * N + n] = (acc[i][j] + bias[n]) * scale;
        }
    }
}

// ---------------- helpers ----------------------------------------------------------
__device__ __forceinline__ float gelu_exact(float v) {
    return 0.5f * v * (1.f + erff(v * 0.7071067811865475f));
}

// ---------------- tx depth/seg prefill: tx[:,256:384] ------------------------------
__global__ __launch_bounds__(256) void ds_fill_kernel(
    const float* __restrict__ dep, const float* __restrict__ seg)
{
    long o = (long)blockIdx.x * 256 + threadIdx.x;   // ROWS*128 total
    long row = o >> 7;
    int j = (int)(o & 127);
    float v = (j < 64) ? dep[row * 64 + j] : seg[row * 64 + j - 64];
    g_tx[row * TCC + 256 + j] = v;
}

// ---------------- ref branch: transform ref_q / ref_v -----------------------------
__global__ __launch_bounds__(256) void refprep_kernel(
    const float* __restrict__ mu, const float* __restrict__ ls)
{
    int i = blockIdx.x * 256 + threadIdx.x;     // 65536 total
    int d = i & 31;
    int f = (i >> 5) & 31;
    int h = (i >> 10) & 7;
    int r = i >> 13;
    int c = h * 32 + d;
    int src = (r * 32 + f) * 512 + c;
    g_refq[i] = mu[c] + expf(ls[c]) * g_refqk[src];
    g_refv[i] = g_refqk[src + 256];
}

// ---------------- ref attention scores: 4 windows per block -----------------------
__global__ __launch_bounds__(256) void ref_scores_kernel()
{
    int blk = blockIdx.x;              // ((r*8+h)*16 + w4)
    int w4 = blk & 15;
    int h = (blk >> 4) & 7;
    int r = blk >> 7;
    __shared__ float rq[32][33];
    __shared__ float qs[4][49][32];
    int t = threadIdx.x;
    const float* rqg = g_refq + (r * 8 + h) * 1024;
    for (int i = t; i < 1024; i += 256) rq[i >> 5][i & 31] = rqg[i];
#pragma unroll
    for (int wi = 0; wi < 4; wi++) {
        int b = r * 64 + w4 * 4 + wi;
        for (int i = t; i < 49 * 32; i += 256) {
            int n = i >> 5, d = i & 31;
            qs[wi][n][d] = g_qkv[(long)(b * 49 + n) * 768 + h * 32 + d] * SCALEF;
        }
    }
    __syncthreads();
    float* op = g_attn + ((long)(r * 8 + h) * 3136 + (w4 * 4) * 49) * 32;
    for (int i = t; i < 4 * 49 * 32; i += 256) {
        int wi = i / (49 * 32);
        int rem = i - wi * 49 * 32;
        int n = rem >> 5, f = rem & 31;
        float s = 0.f;
#pragma unroll
        for (int d = 0; d < 32; d++) s += qs[wi][n][d] * rq[f][d];
        op[i] = s;
    }
}

// =================================================================================
// diffusion conv 3x3 over NCHW [RB, 8, 3136, 32], smem tiling + fused stats.
// =================================================================================
#define CTY 32
__global__ __launch_bounds__(256) void conv_fuse_kernel(
    const float* __restrict__ cw, const float* __restrict__ cb,
    const float* __restrict__ in_att, const float* __restrict__ in_u,
    const float* __restrict__ in_stats, float* __restrict__ out_att,
    float* __restrict__ out_u, float* __restrict__ out_stats)
{
    __shared__ float sin[8][CTY + 2][32];   // 34.8 KB
    __shared__ float ws[576];
    __shared__ float smv[8][2];
    __shared__ float sred[8][8], s2red[8][8];
    const int t = threadIdx.x;
    const int x = t & 31;
    const int yl = t >> 5;                  // 0..7
    const int y0 = blockIdx.x * CTY;
    const int r = blockIdx.y;

    for (int i = t; i < 576; i += 256) ws[i] = cw[i];
    if (in_u && t < 16) smv[t >> 1][t & 1] = in_stats[(r * 8 + (t >> 1)) * 2 + (t & 1)];
    __syncthreads();

    for (int idx = t; idx < 8 * (CTY + 2) * 32; idx += 256) {
        int xx = idx & 31;
        int row = (idx >> 5) % (CTY + 2);
        int ch = idx / ((CTY + 2) * 32);
        int yy = y0 + row - 1;
        float v = 0.f;
        if (yy >= 0 && yy < 3136) {
            long off = ((long)(r * 8 + ch) * 3136 + yy) * 32 + xx;
            v = in_att[off];
            if (in_u) {
                float mean = smv[ch][0] * INVPLANE;
                float var  = smv[ch][1] * INVPLANE - mean * mean;
                float u = (in_u[off] - mean) * rsqrtf(var + 1e-5f);
                v += gelu_exact(u);
                if (row >= 1 && row <= CTY) out_att[off] = v;
            }
        }
        sin[ch][row][xx] = v;
    }
    __syncthreads();

    float acc[8][4];
#pragma unroll
    for (int co = 0; co < 8; co++) {
        float b = cb[co];
#pragma unroll
        for (int yi = 0; yi < 4; yi++) acc[co][yi] = b;
    }

    for (int ci = 0; ci < 8; ci++) {
#pragma unroll
        for (int ky = 0; ky < 3; ky++) {
            float w24[24];
#pragma unroll
            for (int co = 0; co < 8; co++) {
#pragma unroll
                for (int kx = 0; kx < 3; kx++)
                    w24[co * 3 + kx] = ws[(co * 8 + ci) * 9 + ky * 3 + kx];
            }
#pragma unroll
            for (int yi = 0; yi < 4; yi++) {
                int rr = yl + yi * 8 + ky;
                float vm = (x > 0)  ? sin[ci][rr][x - 1] : 0.f;
                float v0 = sin[ci][rr][x];
                float vp = (x < 31) ? sin[ci][rr][x + 1] : 0.f;
#pragma unroll
                for (int co = 0; co < 8; co++)
                    acc[co][yi] += w24[co * 3 + 0] * vm + w24[co * 3 + 1] * v0 + w24[co * 3 + 2] * vp;
            }
        }
    }

    float s[8], s2[8];
#pragma unroll
    for (int co = 0; co < 8; co++) {
        s[co] = 0.f; s2[co] = 0.f;
#pragma unroll
        for (int yi = 0; yi < 4; yi++) {
            int y = y0 + yl + yi * 8;
            out_u[((long)(r * 8 + co) * 3136 + y) * 32 + x] = acc[co][yi];
            s[co]  += acc[co][yi];
            s2[co] += acc[co][yi] * acc[co][yi];
        }
    }
#pragma unroll
    for (int off = 16; off > 0; off >>= 1) {
#pragma unroll
        for (int co = 0; co < 8; co++) {
            s[co]  += __shfl_down_sync(0xffffffffu, s[co], off);
            s2[co] += __shfl_down_sync(0xffffffffu, s2[co], off);
        }
    }
    int wid = t >> 5, lane = t & 31;
    if (lane == 0) {
#pragma unroll
        for (int co = 0; co < 8; co++) { sred[wid][co] = s[co]; s2red[wid][co] = s2[co]; }
    }
    __syncthreads();
    if (t < 8) {
        float a = 0.f, b = 0.f;
#pragma unroll
        for (int w = 0; w < 8; w++) { a += sred[w][t]; b += s2red[w][t]; }
        atomicAdd(&out_stats[(r * 8 + t) * 2],     a);
        atomicAdd(&out_stats[(r * 8 + t) * 2 + 1], b);
    }
}

// ---------------- softmax over NRF (fused final gelu residual) + attn@ref_v -------
__global__ __launch_bounds__(256) void softmax_qnew_kernel(
    const float* __restrict__ in_att, const float* __restrict__ in_u,
    const float* __restrict__ in_stats)
{
    int blk = blockIdx.x;
    int w = blk & 63;
    int h = (blk >> 6) & 7;
    int r = blk >> 9;
    __shared__ __align__(16) float rv[32][32];
    __shared__ __align__(16) float sc[49][33];
    int t = threadIdx.x;
    int p = r * 8 + h;
    float mean = in_stats[p * 2] * INVPLANE;
    float var  = in_stats[p * 2 + 1] * INVPLANE - mean * mean;
    float rstd = rsqrtf(var + 1e-5f);
    const float* rvg = g_refv + p * 1024;
    for (int i = t; i < 1024; i += 256) rv[i >> 5][i & 31] = rvg[i];
    long base = ((long)p * 3136 + w * 49) * 32;
    for (int i = t; i < 49 * 32; i += 256) {
        float u = (in_u[base + i] - mean) * rstd;
        sc[i >> 5][i & 31] = in_att[base + i] + gelu_exact(u);
    }
    __syncthreads();
    {
        int n = t >> 2; if (n > 48) n = 48;
        int q = t & 3;
        int m0 = q * 8;
        float mx = -1e30f;
#pragma unroll
        for (int m = 0; m < 8; m++) mx = fmaxf(mx, sc[n][m0 + m]);
        mx = fmaxf(mx, __shfl_xor_sync(0xffffffffu, mx, 1));
        mx = fmaxf(mx, __shfl_xor_sync(0xffffffffu, mx, 2));
        float s = 0.f;
        float ev[8];
#pragma unroll
        for (int m = 0; m < 8; m++) { ev[m] = expf(sc[n][m0 + m] - mx); s += ev[m]; }
        s += __shfl_xor_sync(0xffffffffu, s, 1);
        s += __shfl_xor_sync(0xffffffffu, s, 2);
        float inv = 1.f / s;
#pragma unroll
        for (int m = 0; m < 8; m++) sc[n][m0 + m] = ev[m] * inv;
    }
    __syncthreads();
    int b = r * 64 + w;
    // AV: units n(49) x dpair(16) = 784, 2-wide d with float2 loads
    for (int u = t; u < 784; u += 256) {
        int n = u >> 4;
        int d0 = (u & 15) * 2;
        float a0 = 0.f, a1 = 0.f;
#pragma unroll
        for (int f = 0; f < 32; f++) {
            float sv = sc[n][f];
            float2 r2 = *(const float2*)&rv[f][d0];
            a0 += sv * r2.x;
            a1 += sv * r2.y;
        }
        *(float2*)&g_s1[(long)(b * 49 + n) * 256 + h * 32 + d0] = make_float2(a0, a1);
    }
}

// ---------------- per-row LN over C=256 (warp-per-row, no barriers) ----------------
__global__ __launch_bounds__(256) void ln_rows_kernel(
    const float* __restrict__ w, const float* __restrict__ bp)
{
    int warp = threadIdx.x >> 5;
    int lane = threadIdx.x & 31;
    int row = blockIdx.x * 8 + warp;
    const float* s1p = g_s1 + (long)row * 256;
    const float* qp  = g_qkv + (long)row * 768;
    float v[8];
    float sum = 0.f;
#pragma unroll
    for (int j = 0; j < 8; j++) {
        int c = j * 32 + lane;
        v[j] = s1p[c] + qp[c];
        sum += v[j];
    }
#pragma unroll
    for (int off = 16; off > 0; off >>= 1) sum += __shfl_xor_sync(0xffffffffu, sum, off);
    float mean = sum * (1.f / 256.f);
    float vs = 0.f;
#pragma unroll
    for (int j = 0; j < 8; j++) { float d = v[j] - mean; vs += d * d; }
#pragma unroll
    for (int off = 16; off > 0; off >>= 1) vs += __shfl_xor_sync(0xffffffffu, vs, off);
    float rstd = rsqrtf(vs * (1.f / 256.f) + 1e-5f);
    float* zp = g_z + (long)row * 256;
#pragma unroll
    for (int j = 0; j < 8; j++) {
        int c = j * 32 + lane;
        zp[c] = (v[j] - mean) * rstd * w[c] + bp[c];
    }
}

// ---------------- window attention, micro-tiled QK / AV, parallel softmax ----------
__global__ __launch_bounds__(256) void win_attn_kernel(const float* __restrict__ rel_bias)
{
    int blk = blockIdx.x;
    int h = blk & 7;
    int b = blk >> 3;
    __shared__ __align__(16) float kk[50][33];   // row 49 zeroed
    __shared__ __align__(16) float vv[49][32];
    __shared__ __align__(16) float qq[49][33];
    __shared__ __align__(16) float pp[49][52];
    int t = threadIdx.x;
    for (int i = t; i < 49 * 32; i += 256) {
        int n = i >> 5, d = i & 31;
        long base = (long)(b * 49 + n) * 768 + h * 32 + d;
        kk[n][d] = g_qkv[base + 256];
        vv[n][d] = g_qkv[base + 512];
        qq[n][d] = g_qn[(long)(b * 49 + n) * 256 + h * 32 + d];
    }
    if (t < 33) kk[49][t] = 0.f;
    __syncthreads();
    // QK: units n(49) x mpair(25) = 1225; each does m0, m0+1
    for (int i = t; i < 1225; i += 256) {
        int n = i / 25;
        int mp = i - n * 25;
        int m0 = mp * 2;
        float a0 = 0.f, a1 = 0.f;
#pragma unroll
        for (int d = 0; d < 32; d++) {
            float qv = qq[n][d];
            a0 += qv * kk[m0][d];
            a1 += qv * kk[m0 + 1][d];
        }
        int in_ = n / 7, jn = n % 7;
        {
            int im = m0 / 7, jm = m0 % 7;
            pp[n][m0] = a0 + rel_bias[((in_ - im + 6) * 13 + (jn - jm + 6)) * 8 + h];
        }
        if (m0 + 1 < 49) {
            int im = (m0 + 1) / 7, jm = (m0 + 1) % 7;
            pp[n][m0 + 1] = a1 + rel_bias[((in_ - im + 6) * 13 + (jn - jm + 6)) * 8 + h];
        }
    }
    __syncthreads();
    {
        int n = t >> 2; if (n > 48) n = 48;
        int q = t & 3;
        int m0 = q * 13;
        int cnt = (q == 3) ? 10 : 13;
        float mx = -1e30f;
        for (int m = 0; m < cnt; m++) mx = fmaxf(mx, pp[n][m0 + m]);
        mx = fmaxf(mx, __shfl_xor_sync(0xffffffffu, mx, 1));
        mx = fmaxf(mx, __shfl_xor_sync(0xffffffffu, mx, 2));
        float s = 0.f;
        float ev[13];
        for (int m = 0; m < cnt; m++) { ev[m] = expf(pp[n][m0 + m] - mx); s += ev[m]; }
        s += __shfl_xor_sync(0xffffffffu, s, 1);
        s += __shfl_xor_sync(0xffffffffu, s, 2);
        float inv = 1.f / s;
        for (int m = 0; m < cnt; m++) pp[n][m0 + m] = ev[m] * inv;
    }
    __syncthreads();
    // AV: units n(49) x dpair(16) = 784, 2-wide d with float2 loads
    for (int u = t; u < 784; u += 256) {
        int n = u >> 4;
        int d0 = (u & 15) * 2;
        float a0 = 0.f, a1 = 0.f;
#pragma unroll
        for (int m = 0; m < 49; m++) {
            float pv = pp[n][m];
            float2 v2 = *(const float2*)&vv[m][d0];
            a0 += pv * v2.x;
            a1 += pv * v2.y;
        }
        *(float2*)&g_av[(long)(b * 49 + n) * 256 + h * 32 + d0] = make_float2(a0, a1);
    }
}

// ---------------- class-token global attention (parallel softmax) -----------------
__global__ __launch_bounds__(256) void cls_attn_kernel()
{
    int blk = blockIdx.x;
    int h = blk & 7;
    int b = blk >> 3;
    __shared__ float tk[49][48], tv[49][48];
    __shared__ float dqh[49][8], sqh[49][8];
    __shared__ float da[8][49], sa[8][49];
    int t = threadIdx.x;
    for (int i = t; i < 49 * 48; i += 256) {
        int n = i / 48, tt = i % 48;
        long base = (long)(b * 49 + n) * 384 + h * 48 + tt;
        tk[n][tt] = g_tk[base];
        tv[n][tt] = g_tv[base];
    }
    for (int i = t; i < 49 * 8; i += 256) {
        int n = i >> 3, c = i & 7;
        dqh[n][c] = g_dq[(long)(b * 49 + n) * 64 + h * 8 + c];
        sqh[n][c] = g_sq[(long)(b * 49 + n) * 64 + h * 8 + c];
    }
    __syncthreads();
    for (int i = t; i < 8 * 48; i += 256) {
        int c = i / 48, tt = i % 48;
        float s = 0.f, s2 = 0.f;
#pragma unroll
        for (int n = 0; n < 49; n++) {
            float kv = tk[n][tt];
            s  += dqh[n][c] * kv;
            s2 += sqh[n][c] * kv;
        }
        da[c][tt] = s;
        sa[c][tt] = s2;
    }
    __syncthreads();
    if (t < 64) {
        int rowid = t >> 2;
        int q = t & 3;
        int c = rowid & 7;
        float* rowp = (rowid < 8) ? da[c] : sa[c];
        int m0 = q * 12;
        float mx = -1e30f;
#pragma unroll
        for (int m = 0; m < 12; m++) mx = fmaxf(mx, rowp[m0 + m]);
        mx = fmaxf(mx, __shfl_xor_sync(0xffffffffu, mx, 1));
        mx = fmaxf(mx, __shfl_xor_sync(0xffffffffu, mx, 2));
        float s = 0.f;
        float ev[12];
#pragma unroll
        for (int m = 0; m < 12; m++) { ev[m] = expf(rowp[m0 + m] - mx); s += ev[m]; }
        s += __shfl_xor_sync(0xffffffffu, s, 1);
        s += __shfl_xor_sync(0xffffffffu, s, 2);
        float inv = 1.f / s;
#pragma unroll
        for (int m = 0; m < 12; m++) rowp[m0 + m] = ev[m] * inv;
    }
    __syncthreads();
    for (int i = t; i < 49 * 8; i += 256) {
        int n = i >> 3, c = i & 7;
        float s = 0.f, s2 = 0.f;
#pragma unroll
        for (int tt = 0; tt < 48; tt++) {
            float vvl = tv[n][tt];
            s  += da[c][tt] * vvl;
            s2 += sa[c][tt] * vvl;
        }
        g_dstok[(long)(b * 49 + n) * 64 + h * 8 + c] = s;
        g_dstok[(long)ROWS * 64 + (long)(b * 49 + n) * 64 + h * 8 + c] = s2;
    }
}

// ---------------- host side --------------------------------------------------------
static void gemm64(const float* A, const float* B, const float* bias,
                   const float* addp, int add_ld, float scale, float* C,
                   int M, int N, int K)
{
    dim3 g(N / 64, M / 64);
    sgemm64<<<g, 256>>>(A, B, bias, addp, add_ld, scale, C, M, N, K);
}

static void gemmT(const float* A, const uint32_t* B, const float* bias,
                  const float* addp, int add_ld, float scale, float* C,
                  float* txout, int M, int N, int K)
{
    dim3 g(N / 128, M / 128, 1);
    mgemm_tf32<<<g, 256>>>(A, B, bias, nullptr, nullptr, addp, add_ld, scale,
                           C, nullptr, txout, M, N, K);
}

static void gemmT_dual(const float* A, const uint32_t* B0, const float* bias0, float* C0,
                       const uint32_t* B1, const float* bias1, float* C1,
                       int M, int N, int K)
{
    dim3 g(N / 128, M / 128, 2);
    mgemm_tf32<<<g, 256>>>(A, B0, bias0, B1, bias1, nullptr, 0, 1.f,
                           C0, C1, nullptr, M, N, K);
}

extern "C" void kernel_launch(void* const* d_in, const int* in_sizes, int n_in,
                              void* d_out, int out_size)
{
    const float* x        = (const float*)d_in[0];
    const float* x_ref    = (const float*)d_in[1];
    const float* depth_t  = (const float*)d_in[2];
    const float* seg_t    = (const float*)d_in[3];
    const float* qkv_w    = (const float*)d_in[4];
    const float* qkv_b    = (const float*)d_in[5];
    const float* proj_w   = (const float*)d_in[6];
    const float* proj_b   = (const float*)d_in[7];
    const float* rel_bias = (const float*)d_in[8];
    const float* diff_mu  = (const float*)d_in[9];
    const float* diff_ls  = (const float*)d_in[10];
    const float* ref_qk_w = (const float*)d_in[11];
    const float* ref_qk_b = (const float*)d_in[12];
    const float* conv_w   = (const float*)d_in[13];
    const float* conv_b   = (const float*)d_in[14];
    const float* q_norm_w = (const float*)d_in[15];
    const float* q_norm_b = (const float*)d_in[16];
    const float* q_proj_w = (const float*)d_in[17];
    const float* q_proj_b = (const float*)d_in[18];
    const float* cdq_w    = (const float*)d_in[19];
    const float* cdq_b    = (const float*)d_in[20];
    const float* csq_w    = (const float*)d_in[21];
    const float* csq_b    = (const float*)d_in[22];
    const float* gk_w     = (const float*)d_in[23];
    const float* gk_b     = (const float*)d_in[24];
    const float* gv_w     = (const float*)d_in[25];
    const float* gv_b     = (const float*)d_in[26];
    const float* pdth_w   = (const float*)d_in[27];
    const float* pdth_b   = (const float*)d_in[28];

    float* out0 = (float*)d_out;                 // [ROWS, 256]
    float* out1 = out0 + (long)ROWS * CDIM;      // d_tok [ROWS, 64]; out2 follows

    float *p_qkv, *p_refqk, *p_z, *p_qn, *p_av, *p_dq, *p_sq,
          *p_tx, *p_tk, *p_tv, *p_dstok, *p_stats,
          *p_attn, *p_attn2, *p_u, *p_u2;
    uint32_t* p_w;
    cudaGetSymbolAddress((void**)&p_qkv,   g_qkv);
    cudaGetSymbolAddress((void**)&p_refqk, g_refqk);
    cudaGetSymbolAddress((void**)&p_z,     g_z);
    cudaGetSymbolAddress((void**)&p_qn,    g_qn);
    cudaGetSymbolAddress((void**)&p_av,    g_av);
    cudaGetSymbolAddress((void**)&p_dq,    g_dq);
    cudaGetSymbolAddress((void**)&p_sq,    g_sq);
    cudaGetSymbolAddress((void**)&p_tx,    g_tx);
    cudaGetSymbolAddress((void**)&p_tk,    g_tk);
    cudaGetSymbolAddress((void**)&p_tv,    g_tv);
    cudaGetSymbolAddress((void**)&p_dstok, g_dstok);
    cudaGetSymbolAddress((void**)&p_stats, g_stats);
    cudaGetSymbolAddress((void**)&p_attn,  g_attn);
    cudaGetSymbolAddress((void**)&p_attn2, g_attn2);
    cudaGetSymbolAddress((void**)&p_u,     g_u);
    cudaGetSymbolAddress((void**)&p_u2,    g_u2);
    cudaGetSymbolAddress((void**)&p_w,     g_wcvt);
    (void)in_sizes; (void)n_in; (void)out_size;

    // 0) pre-convert all tf32 weights
    wconv_kernel<<<768, 256>>>(qkv_w, 196608, WOFF_QKV,
                               ref_qk_w, 131072, WOFF_REFQK,
                               q_proj_w, 65536, WOFF_QPROJ,
                               proj_w, 65536, WOFF_PROJ,
                               gk_w, 147456, WOFF_GK,
                               gv_w, 147456, WOFF_GV);

    // 1) class-token queries (dual launch; depend only on inputs)
    {
        dim3 g(1, ROWS / 64, 2);
        sgemm64_dual<<<g, 256>>>(depth_t, cdq_w, cdq_b, p_dq,
                                 seg_t,   csq_w, csq_b, p_sq,
                                 SCALEF, ROWS, 64, 64);
    }

    // 2) tx depth/seg prefill (independent of everything downstream of out)
    ds_fill_kernel<<<(ROWS * 128) / 256, 256>>>(depth_t, seg_t);

    // 3) ref branch qk projection
    gemmT(x_ref, p_w + WOFF_REFQK, ref_qk_b, nullptr, 0, 1.f, p_refqk, nullptr,
          256, 512, 256);

    // 4) qkv projection: [25088,256] @ [256,768]
    gemmT(x, p_w + WOFF_QKV, qkv_b, nullptr, 0, 1.f, p_qkv, nullptr, ROWS, 768, 256);

    // 5) ref branch prep
    refprep_kernel<<<256, 256>>>(diff_mu, diff_ls);

    // 6) ref-attention scores -> g_attn (att0)   (4 windows / block)
    ref_scores_kernel<<<RB * HH * 16, 256>>>();

    // 7) diffusion (fused LN+gelu residual into next consumer; ping-pong att/u)
    cudaMemsetAsync(p_stats, 0, 3 * RB * HH * 2 * sizeof(float));
    dim3 cgrid(3136 / CTY, RB);
    conv_fuse_kernel<<<cgrid, 256>>>(conv_w, conv_b, p_attn, nullptr, nullptr,
                                     nullptr, p_u, p_stats);
    conv_fuse_kernel<<<cgrid, 256>>>(conv_w, conv_b, p_attn, p_u, p_stats,
                                     p_attn2, p_u2, p_stats + 128);
    conv_fuse_kernel<<<cgrid, 256>>>(conv_w, conv_b, p_attn2, p_u2, p_stats + 128,
                                     p_attn, p_u, p_stats + 256);

    // 8) softmax over NRF (att3 inline) -> s1
    softmax_qnew_kernel<<<RB * HH * NWIN, 256>>>(p_attn, p_u, p_stats + 256);

    // 9) LN(s1 + q_sc) * w + b -> z   (warp-per-row)
    ln_rows_kernel<<<ROWS / 8, 256>>>(q_norm_w, q_norm_b);

    // 10) qn = (z @ q_proj_w + b + q_sc) * SCALE
    gemmT(p_z, p_w + WOFF_QPROJ, q_proj_b, p_qkv, 768, SCALEF, p_qn, nullptr,
          ROWS, 256, 256);

    // 11) window attention -> av [B,N,C]
    win_attn_kernel<<<B_SZ * HH, 256>>>(rel_bias);

    // 12) out = av @ proj_w + proj_b -> d_out segment 0 AND tx[:,0:256]
    gemmT(p_av, p_w + WOFF_PROJ, proj_b, nullptr, 0, 1.f, out0, p_tx,
          ROWS, 256, 256);

    // 13) t_k + t_v in ONE dual GEMM (tx fully assembled)
    gemmT_dual(p_tx, p_w + WOFF_GK, gk_b, p_tk, p_w + WOFF_GV, gv_b, p_tv,
               ROWS, TCC, TCC);

    // 14) class-token attention (depth + seg) -> stacked g_dstok
    cls_attn_kernel<<<B_SZ * HH, 256>>>();

    // 15) final dth projection: one stacked GEMM [2*ROWS,64] @ [64,64] -> out1|out2
    gemm64(p_dstok, pdth_w, pdth_b, nullptr, 0, 1.f, out1, 2 * ROWS, 64, 64);
}

// round 15
// speedup vs baseline: 1.0362x; 1.0362x over previous
#include <cuda_runtime.h>
#include <math.h>
#include <stdint.h>

#define B_SZ 512
#define NTOK 49
#define CDIM 256
#define HH 8
#define DHD 32
#define RB 8
#define NRF 32
#define NWIN 64
#define DCC 64
#define TCC 384
#define ROWS (B_SZ*NTOK)          /* 25088 */
#define SCALEF 0.17677669529663687f
#define PLANE 100352              /* 3136*32 */
#define INVPLANE (1.f/100352.f)

// ---------------- scratch (device globals; no allocation allowed) ----------------
__device__ float g_qkv[ROWS*768];
__device__ float g_refqk[256*512];
__device__ float g_refq[RB*HH*NRF*DHD];
__device__ float g_refv[RB*HH*NRF*DHD];
__device__ float g_attn[RB*HH*NWIN*NTOK*NRF];   // 6,422,528
__device__ float g_attn2[RB*HH*NWIN*NTOK*NRF];
__device__ float g_u[RB*HH*NWIN*NTOK*NRF];
__device__ float g_u2[RB*HH*NWIN*NTOK*NRF];
__device__ float g_stats[3*RB*HH*2];
__device__ float g_s1[ROWS*CDIM];
__device__ float g_z[ROWS*CDIM];
__device__ float g_qn[ROWS*CDIM];
__device__ float g_av[ROWS*CDIM];
__device__ float g_dq[ROWS*DCC];
__device__ float g_sq[ROWS*DCC];
__device__ float g_dstok[2*ROWS*DCC];
__device__ float g_tx[ROWS*TCC];
__device__ float g_tk[ROWS*TCC];
__device__ float g_tv[ROWS*TCC];
// pre-converted tf32 weights
__device__ uint32_t g_wcvt[196608+131072+65536+65536+147456+147456];
#define WOFF_QKV   0
#define WOFF_REFQK 196608
#define WOFF_QPROJ (196608+131072)
#define WOFF_PROJ  (196608+131072+65536)
#define WOFF_GK    (196608+131072+65536+65536)
#define WOFF_GV    (196608+131072+65536+65536+147456)

// =================================================================================
// TF32 tensor-core GEMM (R13 version). B pre-converted tf32. Dual-B via blockIdx.z.
// =================================================================================
__device__ __forceinline__ uint32_t f2tf32(float f) {
    uint32_t r;
    asm("cvt.rna.tf32.f32 %0, %1;" : "=r"(r) : "f"(f));
    return r;
}

__device__ __forceinline__ void mma_tf32(float c[4],
    uint32_t a0, uint32_t a1, uint32_t a2, uint32_t a3,
    uint32_t b0, uint32_t b1)
{
    asm volatile(
        "mma.sync.aligned.m16n8k8.row.col.f32.tf32.tf32.f32 "
        "{%0,%1,%2,%3}, {%4,%5,%6,%7}, {%8,%9}, {%0,%1,%2,%3};"
        : "+f"(c[0]), "+f"(c[1]), "+f"(c[2]), "+f"(c[3])
        : "r"(a0), "r"(a1), "r"(a2), "r"(a3), "r"(b0), "r"(b1));
}

// weight pre-convert
__global__ __launch_bounds__(256) void wconv_kernel(
    const float* __restrict__ w0, int n0, int o0,
    const float* __restrict__ w1, int n1, int o1,
    const float* __restrict__ w2, int n2, int o2,
    const float* __restrict__ w3, int n3, int o3,
    const float* __restrict__ w4, int n4, int o4,
    const float* __restrict__ w5, int n5, int o5)
{
    long i = (long)blockIdx.x * 256 + threadIdx.x;
    if (i < n0) g_wcvt[o0 + i] = f2tf32(w0[i]);
    if (i < n1) g_wcvt[o1 + i] = f2tf32(w1[i]);
    if (i < n2) g_wcvt[o2 + i] = f2tf32(w2[i]);
    if (i < n3) g_wcvt[o3 + i] = f2tf32(w3[i]);
    if (i < n4) g_wcvt[o4 + i] = f2tf32(w4[i]);
    if (i < n5) g_wcvt[o5 + i] = f2tf32(w5[i]);
}

#define APITCH 24
#define BPAD 136
__global__ __launch_bounds__(256, 2) void mgemm_tf32(
    const float* __restrict__ A, const uint32_t* __restrict__ B0_,
    const float* __restrict__ bias0_, const uint32_t* __restrict__ B1_,
    const float* __restrict__ bias1_, const float* __restrict__ addp,
    int add_ld, float scale, float* __restrict__ C0_, float* __restrict__ C1_,
    int M, int N, int K)
{
    const uint32_t* B = (blockIdx.z && B1_) ? B1_ : B0_;
    const float* bias = (blockIdx.z && B1_) ? bias1_ : bias0_;
    float* C = (blockIdx.z && B1_) ? C1_ : C0_;

    __shared__ __align__(16) uint32_t As[2][128][APITCH];
    __shared__ __align__(16) uint32_t Bs[2][8][BPAD];
    const int bm = blockIdx.y * 128;
    const int bn = blockIdx.x * 128;
    const int t = threadIdx.x;
    const int lane = t & 31;
    const int w = t >> 5;
    const int wm = (w >> 2) * 64;
    const int wn = (w & 3) * 32;
    const int g = lane >> 2;
    const int tig = lane & 3;

    const int a_row = t >> 1;
    const int a_k   = (t & 1) * 4;
    const int a_c   = a_k >> 2;
    const int b_k   = t >> 5;
    const int b_n   = (t & 31) * 4;

    const float* Ap = A + (long)(bm + a_row) * K + a_k;
    const uint32_t* Bp = B + (long)b_k * N + bn + b_n;
    const long bstep = (long)8 * N;

    float c[16][4];
#pragma unroll
    for (int i = 0; i < 16; i++)
#pragma unroll
        for (int j = 0; j < 4; j++) c[i][j] = 0.f;

    float4 a_reg;
    uint4 b_reg;

#define STORE_TILE(BUF)                                                  \
    do {                                                                 \
        As[BUF][a_row][0 * 2 + a_c] = f2tf32(a_reg.x);                   \
        As[BUF][a_row][1 * 2 + a_c] = f2tf32(a_reg.y);                   \
        As[BUF][a_row][2 * 2 + a_c] = f2tf32(a_reg.z);                   \
        As[BUF][a_row][3 * 2 + a_c] = f2tf32(a_reg.w);                   \
        *(uint4*)&Bs[BUF][b_k][b_n] = b_reg;                             \
    } while (0)

#define COMPUTE_TILE(BUF)                                                \
    do {                                                                 \
        uint32_t af[4][4];                                               \
        _Pragma("unroll")                                                \
        for (int mi = 0; mi < 4; mi++) {                                 \
            int m0 = wm + mi * 16 + g;                                   \
            uint2 pa = *(const uint2*)&As[BUF][m0][tig * 2];             \
            uint2 pb = *(const uint2*)&As[BUF][m0 + 8][tig * 2];         \
            af[mi][0] = pa.x;                                            \
            af[mi][1] = pb.x;                                            \
            af[mi][2] = pa.y;                                            \
            af[mi][3] = pb.y;                                            \
        }                                                                \
        uint32_t bf[4][2];                                               \
        _Pragma("unroll")                                                \
        for (int ni = 0; ni < 4; ni++) {                                 \
            int n0 = wn + ni * 8 + g;                                    \
            bf[ni][0] = Bs[BUF][tig][n0];                                \
            bf[ni][1] = Bs[BUF][tig + 4][n0];                            \
        }                                                                \
        _Pragma("unroll")                                                \
        for (int mi = 0; mi < 4; mi++)                                   \
            _Pragma("unroll")                                            \
            for (int ni = 0; ni < 4; ni++)                               \
                mma_tf32(c[mi * 4 + ni], af[mi][0], af[mi][1],           \
                         af[mi][2], af[mi][3], bf[ni][0], bf[ni][1]);    \
    } while (0)

    a_reg = *(const float4*)Ap;
    b_reg = *(const uint4*)Bp;
    STORE_TILE(0);
    __syncthreads();

    const int nk = K >> 3;               // EVEN for all call sites
    for (int kt = 0; kt < nk; kt += 2) {
        a_reg = *(const float4*)(Ap + (kt + 1) * 8);
        b_reg = *(const uint4*)(Bp + (long)(kt + 1) * bstep);
        COMPUTE_TILE(0);
        STORE_TILE(1);
        __syncthreads();
        bool more = (kt + 2) < nk;
        if (more) {
            a_reg = *(const float4*)(Ap + (kt + 2) * 8);
            b_reg = *(const uint4*)(Bp + (long)(kt + 2) * bstep);
        }
        COMPUTE_TILE(1);
        if (more) {
            STORE_TILE(0);
            __syncthreads();
        }
    }
#undef STORE_TILE
#undef COMPUTE_TILE

#pragma unroll
    for (int mi = 0; mi < 4; mi++) {
#pragma unroll
        for (int ni = 0; ni < 4; ni++) {
            int n = bn + wn + ni * 8 + tig * 2;
            float b0 = bias[n], b1 = bias[n + 1];
            int m1 = bm + wm + mi * 16 + g;
            int m2 = m1 + 8;
            float v0 = c[mi * 4 + ni][0] + b0;
            float v1 = c[mi * 4 + ni][1] + b1;
            float v2 = c[mi * 4 + ni][2] + b0;
            float v3 = c[mi * 4 + ni][3] + b1;
            if (addp) {
                const float* ar1 = addp + (long)m1 * add_ld + n;
                const float* ar2 = addp + (long)m2 * add_ld + n;
                v0 += ar1[0]; v1 += ar1[1];
                v2 += ar2[0]; v3 += ar2[1];
            }
            *(float2*)(C + (long)m1 * N + n) = make_float2(v0 * scale, v1 * scale);
            *(float2*)(C + (long)m2 * N + n) = make_float2(v2 * scale, v3 * scale);
        }
    }
}

// ---------------- 64x64 tiled SGEMM (small GEMMs) ---------------------------------
__global__ __launch_bounds__(256) void sgemm64(
    const float* __restrict__ A, const float* __restrict__ B,
    const float* __restrict__ bias, const float* __restrict__ addp,
    int add_ld, float scale, float* __restrict__ C,
    int M, int N, int K)
{
    __shared__ __align__(16) float As[16][64];
    __shared__ __align__(16) float Bs[16][64];
    const int bm = blockIdx.y * 64;
    const int bn = blockIdx.x * 64;
    const int t  = threadIdx.x;
    const int tx = t & 15, ty = t >> 4;
    const int a_m = t >> 2, a_k = (t & 3) << 2;
    const int b_k = t >> 4, b_n = (t & 15) << 2;

    float acc[4][4];
#pragma unroll
    for (int i = 0; i < 4; i++)
#pragma unroll
        for (int j = 0; j < 4; j++) acc[i][j] = 0.f;

    const float* Aptr = A + (long)(bm + a_m) * K + a_k;
    const float* Bptr = B + (long)b_k * N + bn + b_n;

    for (int k0 = 0; k0 < K; k0 += 16) {
        float4 av = *(const float4*)(Aptr + k0);
        As[a_k + 0][a_m] = av.x;
        As[a_k + 1][a_m] = av.y;
        As[a_k + 2][a_m] = av.z;
        As[a_k + 3][a_m] = av.w;
        *(float4*)&Bs[b_k][b_n] = *(const float4*)(Bptr + (long)k0 * N);
        __syncthreads();
#pragma unroll
        for (int kk = 0; kk < 16; kk++) {
            float4 a4 = *(const float4*)&As[kk][ty << 2];
            float4 b4 = *(const float4*)&Bs[kk][tx << 2];
            acc[0][0] += a4.x * b4.x; acc[0][1] += a4.x * b4.y;
            acc[0][2] += a4.x * b4.z; acc[0][3] += a4.x * b4.w;
            acc[1][0] += a4.y * b4.x; acc[1][1] += a4.y * b4.y;
            acc[1][2] += a4.y * b4.z; acc[1][3] += a4.y * b4.w;
            acc[2][0] += a4.z * b4.x; acc[2][1] += a4.z * b4.y;
            acc[2][2] += a4.z * b4.z; acc[2][3] += a4.z * b4.w;
            acc[3][0] += a4.w * b4.x; acc[3][1] += a4.w * b4.y;
            acc[3][2] += a4.w * b4.z; acc[3][3] += a4.w * b4.w;
        }
        __syncthreads();
    }
#pragma unroll
    for (int i = 0; i < 4; i++) {
        int m = bm + (ty << 2) + i;
#pragma unroll
        for (int j = 0; j < 4; j++) {
            int n = bn + (tx << 2) + j;
            float v = acc[i][j] + bias[n];
            if (addp) v += addp[(long)m * add_ld + n];
            C[(long)m * N + n] = v * scale;
        }
    }
}

// ---------------- dual small SGEMM: z selects operand set -------------------------
__global__ __launch_bounds__(256) void sgemm64_dual(
    const float* __restrict__ A0, const float* __restrict__ B0,
    const float* __restrict__ bias0, float* __restrict__ C0,
    const float* __restrict__ A1, const float* __restrict__ B1,
    const float* __restrict__ bias1, float* __restrict__ C1,
    float scale, int M, int N, int K)
{
    const float* A = blockIdx.z ? A1 : A0;
    const float* B = blockIdx.z ? B1 : B0;
    const float* bias = blockIdx.z ? bias1 : bias0;
    float* C = blockIdx.z ? C1 : C0;

    __shared__ __align__(16) float As[16][64];
    __shared__ __align__(16) float Bs[16][64];
    const int bm = blockIdx.y * 64;
    const int bn = blockIdx.x * 64;
    const int t  = threadIdx.x;
    const int tx = t & 15, ty = t >> 4;
    const int a_m = t >> 2, a_k = (t & 3) << 2;
    const int b_k = t >> 4, b_n = (t & 15) << 2;

    float acc[4][4];
#pragma unroll
    for (int i = 0; i < 4; i++)
#pragma unroll
        for (int j = 0; j < 4; j++) acc[i][j] = 0.f;

    const float* Aptr = A + (long)(bm + a_m) * K + a_k;
    const float* Bptr = B + (long)b_k * N + bn + b_n;

    for (int k0 = 0; k0 < K; k0 += 16) {
        float4 av = *(const float4*)(Aptr + k0);
        As[a_k + 0][a_m] = av.x;
        As[a_k + 1][a_m] = av.y;
        As[a_k + 2][a_m] = av.z;
        As[a_k + 3][a_m] = av.w;
        *(float4*)&Bs[b_k][b_n] = *(const float4*)(Bptr + (long)k0 * N);
        __syncthreads();
#pragma unroll
        for (int kk = 0; kk < 16; kk++) {
            float4 a4 = *(const float4*)&As[kk][ty << 2];
            float4 b4 = *(const float4*)&Bs[kk][tx << 2];
            acc[0][0] += a4.x * b4.x; acc[0][1] += a4.x * b4.y;
            acc[0][2] += a4.x * b4.z; acc[0][3] += a4.x * b4.w;
            acc[1][0] += a4.y * b4.x; acc[1][1] += a4.y * b4.y;
            acc[1][2] += a4.y * b4.z; acc[1][3] += a4.y * b4.w;
            acc[2][0] += a4.z * b4.x; acc[2][1] += a4.z * b4.y;
            acc[2][2] += a4.z * b4.z; acc[2][3] += a4.z * b4.w;
            acc[3][0] += a4.w * b4.x; acc[3][1] += a4.w * b4.y;
            acc[3][2] += a4.w * b4.z; acc[3][3] += a4.w * b4.w;
        }
        __syncthreads();
    }
#pragma unroll
    for (int i = 0; i < 4; i++) {
        int m = bm + (ty << 2) + i;
#pragma unroll
        for (int j = 0; j < 4; j++) {
            int n = bn + (tx << 2) + j;
            C[(long)m * N + n] = (acc[i][j] + bias[n]) * scale;
        }
    }
}

// ---------------- helpers ----------------------------------------------------------
__device__ __forceinline__ float gelu_exact(float v) {
    return 0.5f * v * (1.f + erff(v * 0.7071067811865475f));
}

// ---------------- ref branch: transform ref_q / ref_v -----------------------------
__global__ __launch_bounds__(256) void refprep_kernel(
    const float* __restrict__ mu, const float* __restrict__ ls)
{
    int i = blockIdx.x * 256 + threadIdx.x;     // 65536 total
    int d = i & 31;
    int f = (i >> 5) & 31;
    int h = (i >> 10) & 7;
    int r = i >> 13;
    int c = h * 32 + d;
    int src = (r * 32 + f) * 512 + c;
    g_refq[i] = mu[c] + expf(ls[c]) * g_refqk[src];
    g_refv[i] = g_refqk[src + 256];
}

// ---------------- ref attention scores: 4 windows per block -----------------------
__global__ __launch_bounds__(256) void ref_scores_kernel()
{
    int blk = blockIdx.x;              // ((r*8+h)*16 + w4)
    int w4 = blk & 15;
    int h = (blk >> 4) & 7;
    int r = blk >> 7;
    __shared__ float rq[32][33];
    __shared__ float qs[4][49][32];
    int t = threadIdx.x;
    const float* rqg = g_refq + (r * 8 + h) * 1024;
    for (int i = t; i < 1024; i += 256) rq[i >> 5][i & 31] = rqg[i];
#pragma unroll
    for (int wi = 0; wi < 4; wi++) {
        int b = r * 64 + w4 * 4 + wi;
        for (int i = t; i < 49 * 32; i += 256) {
            int n = i >> 5, d = i & 31;
            qs[wi][n][d] = g_qkv[(long)(b * 49 + n) * 768 + h * 32 + d] * SCALEF;
        }
    }
    __syncthreads();
    float* op = g_attn + ((long)(r * 8 + h) * 3136 + (w4 * 4) * 49) * 32;
    for (int i = t; i < 4 * 49 * 32; i += 256) {
        int wi = i / (49 * 32);
        int rem = i - wi * 49 * 32;
        int n = rem >> 5, f = rem & 31;
        float s = 0.f;
#pragma unroll
        for (int d = 0; d < 32; d++) s += qs[wi][n][d] * rq[f][d];
        op[i] = s;
    }
}

// =================================================================================
// diffusion conv 3x3 over NCHW [RB, 8, 3136, 32], smem tiling + fused stats.
// =================================================================================
#define CTY 32
__global__ __launch_bounds__(256) void conv_fuse_kernel(
    const float* __restrict__ cw, const float* __restrict__ cb,
    const float* __restrict__ in_att, const float* __restrict__ in_u,
    const float* __restrict__ in_stats, float* __restrict__ out_att,
    float* __restrict__ out_u, float* __restrict__ out_stats)
{
    __shared__ float sin[8][CTY + 2][32];   // 34.8 KB
    __shared__ float ws[576];
    __shared__ float smv[8][2];
    __shared__ float sred[8][8], s2red[8][8];
    const int t = threadIdx.x;
    const int x = t & 31;
    const int yl = t >> 5;                  // 0..7
    const int y0 = blockIdx.x * CTY;
    const int r = blockIdx.y;

    for (int i = t; i < 576; i += 256) ws[i] = cw[i];
    if (in_u && t < 16) smv[t >> 1][t & 1] = in_stats[(r * 8 + (t >> 1)) * 2 + (t & 1)];
    __syncthreads();

    for (int idx = t; idx < 8 * (CTY + 2) * 32; idx += 256) {
        int xx = idx & 31;
        int row = (idx >> 5) % (CTY + 2);
        int ch = idx / ((CTY + 2) * 32);
        int yy = y0 + row - 1;
        float v = 0.f;
        if (yy >= 0 && yy < 3136) {
            long off = ((long)(r * 8 + ch) * 3136 + yy) * 32 + xx;
            v = in_att[off];
            if (in_u) {
                float mean = smv[ch][0] * INVPLANE;
                float var  = smv[ch][1] * INVPLANE - mean * mean;
                float u = (in_u[off] - mean) * rsqrtf(var + 1e-5f);
                v += gelu_exact(u);
                if (row >= 1 && row <= CTY) out_att[off] = v;
            }
        }
        sin[ch][row][xx] = v;
    }
    __syncthreads();

    float acc[8][4];
#pragma unroll
    for (int co = 0; co < 8; co++) {
        float b = cb[co];
#pragma unroll
        for (int yi = 0; yi < 4; yi++) acc[co][yi] = b;
    }

    for (int ci = 0; ci < 8; ci++) {
#pragma unroll
        for (int ky = 0; ky < 3; ky++) {
            float w24[24];
#pragma unroll
            for (int co = 0; co < 8; co++) {
#pragma unroll
                for (int kx = 0; kx < 3; kx++)
                    w24[co * 3 + kx] = ws[(co * 8 + ci) * 9 + ky * 3 + kx];
            }
#pragma unroll
            for (int yi = 0; yi < 4; yi++) {
                int rr = yl + yi * 8 + ky;
                float vm = (x > 0)  ? sin[ci][rr][x - 1] : 0.f;
                float v0 = sin[ci][rr][x];
                float vp = (x < 31) ? sin[ci][rr][x + 1] : 0.f;
#pragma unroll
                for (int co = 0; co < 8; co++)
                    acc[co][yi] += w24[co * 3 + 0] * vm + w24[co * 3 + 1] * v0 + w24[co * 3 + 2] * vp;
            }
        }
    }

    float s[8], s2[8];
#pragma unroll
    for (int co = 0; co < 8; co++) {
        s[co] = 0.f; s2[co] = 0.f;
#pragma unroll
        for (int yi = 0; yi < 4; yi++) {
            int y = y0 + yl + yi * 8;
            out_u[((long)(r * 8 + co) * 3136 + y) * 32 + x] = acc[co][yi];
            s[co]  += acc[co][yi];
            s2[co] += acc[co][yi] * acc[co][yi];
        }
    }
#pragma unroll
    for (int off = 16; off > 0; off >>= 1) {
#pragma unroll
        for (int co = 0; co < 8; co++) {
            s[co]  += __shfl_down_sync(0xffffffffu, s[co], off);
            s2[co] += __shfl_down_sync(0xffffffffu, s2[co], off);
        }
    }
    int wid = t >> 5, lane = t & 31;
    if (lane == 0) {
#pragma unroll
        for (int co = 0; co < 8; co++) { sred[wid][co] = s[co]; s2red[wid][co] = s2[co]; }
    }
    __syncthreads();
    if (t < 8) {
        float a = 0.f, b = 0.f;
#pragma unroll
        for (int w = 0; w < 8; w++) { a += sred[w][t]; b += s2red[w][t]; }
        atomicAdd(&out_stats[(r * 8 + t) * 2],     a);
        atomicAdd(&out_stats[(r * 8 + t) * 2 + 1], b);
    }
}

// ---------------- softmax over NRF (fused final gelu residual) + attn@ref_v -------
__global__ __launch_bounds__(256) void softmax_qnew_kernel(
    const float* __restrict__ in_att, const float* __restrict__ in_u,
    const float* __restrict__ in_stats)
{
    int blk = blockIdx.x;
    int w = blk & 63;
    int h = (blk >> 6) & 7;
    int r = blk >> 9;
    __shared__ float rv[32][32];
    __shared__ float sc[49][33];
    int t = threadIdx.x;
    int p = r * 8 + h;
    float mean = in_stats[p * 2] * INVPLANE;
    float var  = in_stats[p * 2 + 1] * INVPLANE - mean * mean;
    float rstd = rsqrtf(var + 1e-5f);
    const float* rvg = g_refv + p * 1024;
    for (int i = t; i < 1024; i += 256) rv[i >> 5][i & 31] = rvg[i];
    long base = ((long)p * 3136 + w * 49) * 32;
    for (int i = t; i < 49 * 32; i += 256) {
        float u = (in_u[base + i] - mean) * rstd;
        sc[i >> 5][i & 31] = in_att[base + i] + gelu_exact(u);
    }
    __syncthreads();
    {
        int n = t >> 2; if (n > 48) n = 48;
        int q = t & 3;
        int m0 = q * 8;
        float mx = -1e30f;
#pragma unroll
        for (int m = 0; m < 8; m++) mx = fmaxf(mx, sc[n][m0 + m]);
        mx = fmaxf(mx, __shfl_xor_sync(0xffffffffu, mx, 1));
        mx = fmaxf(mx, __shfl_xor_sync(0xffffffffu, mx, 2));
        float s = 0.f;
        float ev[8];
#pragma unroll
        for (int m = 0; m < 8; m++) { ev[m] = expf(sc[n][m0 + m] - mx); s += ev[m]; }
        s += __shfl_xor_sync(0xffffffffu, s, 1);
        s += __shfl_xor_sync(0xffffffffu, s, 2);
        float inv = 1.f / s;
#pragma unroll
        for (int m = 0; m < 8; m++) sc[n][m0 + m] = ev[m] * inv;
    }
    __syncthreads();
    int b = r * 64 + w;
    for (int i = t; i < 49 * 32; i += 256) {
        int n = i >> 5, d = i & 31;
        float s = 0.f;
#pragma unroll
        for (int f = 0; f < 32; f++) s += sc[n][f] * rv[f][d];
        g_s1[(long)(b * 49 + n) * 256 + h * 32 + d] = s;
    }
}

// ---------------- per-row LN over C=256 (warp-per-row, no barriers) ----------------
__global__ __launch_bounds__(256) void ln_rows_kernel(
    const float* __restrict__ w, const float* __restrict__ bp)
{
    int warp = threadIdx.x >> 5;
    int lane = threadIdx.x & 31;
    int row = blockIdx.x * 8 + warp;
    const float* s1p = g_s1 + (long)row * 256;
    const float* qp  = g_qkv + (long)row * 768;
    float v[8];
    float sum = 0.f;
#pragma unroll
    for (int j = 0; j < 8; j++) {
        int c = j * 32 + lane;
        v[j] = s1p[c] + qp[c];
        sum += v[j];
    }
#pragma unroll
    for (int off = 16; off > 0; off >>= 1) sum += __shfl_xor_sync(0xffffffffu, sum, off);
    float mean = sum * (1.f / 256.f);
    float vs = 0.f;
#pragma unroll
    for (int j = 0; j < 8; j++) { float d = v[j] - mean; vs += d * d; }
#pragma unroll
    for (int off = 16; off > 0; off >>= 1) vs += __shfl_xor_sync(0xffffffffu, vs, off);
    float rstd = rsqrtf(vs * (1.f / 256.f) + 1e-5f);
    float* zp = g_z + (long)row * 256;
#pragma unroll
    for (int j = 0; j < 8; j++) {
        int c = j * 32 + lane;
        zp[c] = (v[j] - mean) * rstd * w[c] + bp[c];
    }
}

// ---------------- window attention (49x49 per (b,h)), parallel softmax -------------
__global__ __launch_bounds__(256) void win_attn_kernel(const float* __restrict__ rel_bias)
{
    int blk = blockIdx.x;
    int h = blk & 7;
    int b = blk >> 3;
    __shared__ float kk[49][33];
    __shared__ float vv[49][32];
    __shared__ float qq[49][33];
    __shared__ float pp[49][52];
    int t = threadIdx.x;
    for (int i = t; i < 49 * 32; i += 256) {
        int n = i >> 5, d = i & 31;
        long base = (long)(b * 49 + n) * 768 + h * 32 + d;
        kk[n][d] = g_qkv[base + 256];
        vv[n][d] = g_qkv[base + 512];
        qq[n][d] = g_qn[(long)(b * 49 + n) * 256 + h * 32 + d];
    }
    __syncthreads();
    for (int i = t; i < 49 * 49; i += 256) {
        int n = i / 49, m = i % 49;
        float s = 0.f;
#pragma unroll
        for (int d = 0; d < 32; d++) s += qq[n][d] * kk[m][d];
        int in_ = n / 7, jn = n % 7, im = m / 7, jm = m % 7;
        s += rel_bias[((in_ - im + 6) * 13 + (jn - jm + 6)) * 8 + h];
        pp[n][m] = s;
    }
    __syncthreads();
    {
        int n = t >> 2; if (n > 48) n = 48;
        int q = t & 3;
        int m0 = q * 13;
        int cnt = (q == 3) ? 10 : 13;
        float mx = -1e30f;
        for (int m = 0; m < cnt; m++) mx = fmaxf(mx, pp[n][m0 + m]);
        mx = fmaxf(mx, __shfl_xor_sync(0xffffffffu, mx, 1));
        mx = fmaxf(mx, __shfl_xor_sync(0xffffffffu, mx, 2));
        float s = 0.f;
        float ev[13];
        for (int m = 0; m < cnt; m++) { ev[m] = expf(pp[n][m0 + m] - mx); s += ev[m]; }
        s += __shfl_xor_sync(0xffffffffu, s, 1);
        s += __shfl_xor_sync(0xffffffffu, s, 2);
        float inv = 1.f / s;
        for (int m = 0; m < cnt; m++) pp[n][m0 + m] = ev[m] * inv;
    }
    __syncthreads();
    for (int i = t; i < 49 * 32; i += 256) {
        int n = i >> 5, d = i & 31;
        float s = 0.f;
#pragma unroll
        for (int m = 0; m < 49; m++) s += pp[n][m] * vv[m][d];
        g_av[(long)(b * 49 + n) * 256 + h * 32 + d] = s;
    }
}

// ---------------- concat [out | depth | seg] -> t_x --------------------------------
__global__ __launch_bounds__(256) void concat_kernel(
    const float* __restrict__ outp, const float* __restrict__ dep,
    const float* __restrict__ seg)
{
    long o = (long)blockIdx.x * 256 + threadIdx.x;
    int j = (int)(o % 384);
    long row = o / 384;
    float v;
    if (j < 256)      v = outp[row * 256 + j];
    else if (j < 320) v = dep[row * 64 + j - 256];
    else              v = seg[row * 64 + j - 320];
    g_tx[o] = v;
}

// ---------------- class-token global attention (parallel softmax) -----------------
__global__ __launch_bounds__(256) void cls_attn_kernel()
{
    int blk = blockIdx.x;
    int h = blk & 7;
    int b = blk >> 3;
    __shared__ float tk[49][48], tv[49][48];
    __shared__ float dqh[49][8], sqh[49][8];
    __shared__ float da[8][49], sa[8][49];
    int t = threadIdx.x;
    for (int i = t; i < 49 * 48; i += 256) {
        int n = i / 48, tt = i % 48;
        long base = (long)(b * 49 + n) * 384 + h * 48 + tt;
        tk[n][tt] = g_tk[base];
        tv[n][tt] = g_tv[base];
    }
    for (int i = t; i < 49 * 8; i += 256) {
        int n = i >> 3, c = i & 7;
        dqh[n][c] = g_dq[(long)(b * 49 + n) * 64 + h * 8 + c];
        sqh[n][c] = g_sq[(long)(b * 49 + n) * 64 + h * 8 + c];
    }
    __syncthreads();
    for (int i = t; i < 8 * 48; i += 256) {
        int c = i / 48, tt = i % 48;
        float s = 0.f, s2 = 0.f;
#pragma unroll
        for (int n = 0; n < 49; n++) {
            float kv = tk[n][tt];
            s  += dqh[n][c] * kv;
            s2 += sqh[n][c] * kv;
        }
        da[c][tt] = s;
        sa[c][tt] = s2;
    }
    __syncthreads();
    if (t < 64) {
        int rowid = t >> 2;
        int q = t & 3;
        int c = rowid & 7;
        float* rowp = (rowid < 8) ? da[c] : sa[c];
        int m0 = q * 12;
        float mx = -1e30f;
#pragma unroll
        for (int m = 0; m < 12; m++) mx = fmaxf(mx, rowp[m0 + m]);
        mx = fmaxf(mx, __shfl_xor_sync(0xffffffffu, mx, 1));
        mx = fmaxf(mx, __shfl_xor_sync(0xffffffffu, mx, 2));
        float s = 0.f;
        float ev[12];
#pragma unroll
        for (int m = 0; m < 12; m++) { ev[m] = expf(rowp[m0 + m] - mx); s += ev[m]; }
        s += __shfl_xor_sync(0xffffffffu, s, 1);
        s += __shfl_xor_sync(0xffffffffu, s, 2);
        float inv = 1.f / s;
#pragma unroll
        for (int m = 0; m < 12; m++) rowp[m0 + m] = ev[m] * inv;
    }
    __syncthreads();
    for (int i = t; i < 49 * 8; i += 256) {
        int n = i >> 3, c = i & 7;
        float s = 0.f, s2 = 0.f;
#pragma unroll
        for (int tt = 0; tt < 48; tt++) {
            float vvl = tv[n][tt];
            s  += da[c][tt] * vvl;
            s2 += sa[c][tt] * vvl;
        }
        g_dstok[(long)(b * 49 + n) * 64 + h * 8 + c] = s;
        g_dstok[(long)ROWS * 64 + (long)(b * 49 + n) * 64 + h * 8 + c] = s2;
    }
}

// ---------------- host side --------------------------------------------------------
static void gemm64(const float* A, const float* B, const float* bias,
                   const float* addp, int add_ld, float scale, float* C,
                   int M, int N, int K)
{
    dim3 g(N / 64, M / 64);
    sgemm64<<<g, 256>>>(A, B, bias, addp, add_ld, scale, C, M, N, K);
}

static void gemmT(const float* A, const uint32_t* B, const float* bias,
                  const float* addp, int add_ld, float scale, float* C,
                  int M, int N, int K)
{
    dim3 g(N / 128, M / 128, 1);
    mgemm_tf32<<<g, 256>>>(A, B, bias, nullptr, nullptr, addp, add_ld, scale,
                           C, nullptr, M, N, K);
}

static void gemmT_dual(const float* A, const uint32_t* B0, const float* bias0, float* C0,
                       const uint32_t* B1, const float* bias1, float* C1,
                       int M, int N, int K)
{
    dim3 g(N / 128, M / 128, 2);
    mgemm_tf32<<<g, 256>>>(A, B0, bias0, B1, bias1, nullptr, 0, 1.f,
                           C0, C1, M, N, K);
}

extern "C" void kernel_launch(void* const* d_in, const int* in_sizes, int n_in,
                              void* d_out, int out_size)
{
    const float* x        = (const float*)d_in[0];
    const float* x_ref    = (const float*)d_in[1];
    const float* depth_t  = (const float*)d_in[2];
    const float* seg_t    = (const float*)d_in[3];
    const float* qkv_w    = (const float*)d_in[4];
    const float* qkv_b    = (const float*)d_in[5];
    const float* proj_w   = (const float*)d_in[6];
    const float* proj_b   = (const float*)d_in[7];
    const float* rel_bias = (const float*)d_in[8];
    const float* diff_mu  = (const float*)d_in[9];
    const float* diff_ls  = (const float*)d_in[10];
    const float* ref_qk_w = (const float*)d_in[11];
    const float* ref_qk_b = (const float*)d_in[12];
    const float* conv_w   = (const float*)d_in[13];
    const float* conv_b   = (const float*)d_in[14];
    const float* q_norm_w = (const float*)d_in[15];
    const float* q_norm_b = (const float*)d_in[16];
    const float* q_proj_w = (const float*)d_in[17];
    const float* q_proj_b = (const float*)d_in[18];
    const float* cdq_w    = (const float*)d_in[19];
    const float* cdq_b    = (const float*)d_in[20];
    const float* csq_w    = (const float*)d_in[21];
    const float* csq_b    = (const float*)d_in[22];
    const float* gk_w     = (const float*)d_in[23];
    const float* gk_b     = (const float*)d_in[24];
    const float* gv_w     = (const float*)d_in[25];
    const float* gv_b     = (const float*)d_in[26];
    const float* pdth_w   = (const float*)d_in[27];
    const float* pdth_b   = (const float*)d_in[28];

    float* out0 = (float*)d_out;                 // [ROWS, 256]
    float* out1 = out0 + (long)ROWS * CDIM;      // d_tok [ROWS, 64]; out2 follows

    float *p_qkv, *p_refqk, *p_z, *p_qn, *p_av, *p_dq, *p_sq,
          *p_tx, *p_tk, *p_tv, *p_dstok, *p_stats,
          *p_attn, *p_attn2, *p_u, *p_u2;
    uint32_t* p_w;
    cudaGetSymbolAddress((void**)&p_qkv,   g_qkv);
    cudaGetSymbolAddress((void**)&p_refqk, g_refqk);
    cudaGetSymbolAddress((void**)&p_z,     g_z);
    cudaGetSymbolAddress((void**)&p_qn,    g_qn);
    cudaGetSymbolAddress((void**)&p_av,    g_av);
    cudaGetSymbolAddress((void**)&p_dq,    g_dq);
    cudaGetSymbolAddress((void**)&p_sq,    g_sq);
    cudaGetSymbolAddress((void**)&p_tx,    g_tx);
    cudaGetSymbolAddress((void**)&p_tk,    g_tk);
    cudaGetSymbolAddress((void**)&p_tv,    g_tv);
    cudaGetSymbolAddress((void**)&p_dstok, g_dstok);
    cudaGetSymbolAddress((void**)&p_stats, g_stats);
    cudaGetSymbolAddress((void**)&p_attn,  g_attn);
    cudaGetSymbolAddress((void**)&p_attn2, g_attn2);
    cudaGetSymbolAddress((void**)&p_u,     g_u);
    cudaGetSymbolAddress((void**)&p_u2,    g_u2);
    cudaGetSymbolAddress((void**)&p_w,     g_wcvt);
    (void)in_sizes; (void)n_in; (void)out_size;

    // 0) pre-convert all tf32 weights
    wconv_kernel<<<768, 256>>>(qkv_w, 196608, WOFF_QKV,
                               ref_qk_w, 131072, WOFF_REFQK,
                               q_proj_w, 65536, WOFF_QPROJ,
                               proj_w, 65536, WOFF_PROJ,
                               gk_w, 147456, WOFF_GK,
                               gv_w, 147456, WOFF_GV);

    // 1) class-token queries (dual launch; depend only on inputs)
    {
        dim3 g(1, ROWS / 64, 2);
        sgemm64_dual<<<g, 256>>>(depth_t, cdq_w, cdq_b, p_dq,
                                 seg_t,   csq_w, csq_b, p_sq,
                                 SCALEF, ROWS, 64, 64);
    }

    // 2) ref branch qk projection — fp32 sgemm64: 32 blocks vs 8 for the tf32
    //    kernel; this GEMM is latency-bound (measured 25us at grid=8), and more
    //    CTAs beat tensor cores at this size. fp32 also improves accuracy here.
    gemm64(x_ref, ref_qk_w, ref_qk_b, nullptr, 0, 1.f, p_refqk, 256, 512, 256);

    // 3) qkv projection: [25088,256] @ [256,768]
    gemmT(x, p_w + WOFF_QKV, qkv_b, nullptr, 0, 1.f, p_qkv, ROWS, 768, 256);

    // 4) ref branch prep
    refprep_kernel<<<256, 256>>>(diff_mu, diff_ls);

    // 5) ref-attention scores -> g_attn (att0)   (4 windows / block)
    ref_scores_kernel<<<RB * HH * 16, 256>>>();

    // 6) diffusion (fused LN+gelu residual into next consumer; ping-pong att/u)
    cudaMemsetAsync(p_stats, 0, 3 * RB * HH * 2 * sizeof(float));
    dim3 cgrid(3136 / CTY, RB);
    conv_fuse_kernel<<<cgrid, 256>>>(conv_w, conv_b, p_attn, nullptr, nullptr,
                                     nullptr, p_u, p_stats);
    conv_fuse_kernel<<<cgrid, 256>>>(conv_w, conv_b, p_attn, p_u, p_stats,
                                     p_attn2, p_u2, p_stats + 128);
    conv_fuse_kernel<<<cgrid, 256>>>(conv_w, conv_b, p_attn2, p_u2, p_stats + 128,
                                     p_attn, p_u, p_stats + 256);

    // 7) softmax over NRF (att3 inline) -> s1
    softmax_qnew_kernel<<<RB * HH * NWIN, 256>>>(p_attn, p_u, p_stats + 256);

    // 8) LN(s1 + q_sc) * w + b -> z   (warp-per-row)
    ln_rows_kernel<<<ROWS / 8, 256>>>(q_norm_w, q_norm_b);

    // 9) qn = (z @ q_proj_w + b + q_sc) * SCALE
    gemmT(p_z, p_w + WOFF_QPROJ, q_proj_b, p_qkv, 768, SCALEF, p_qn, ROWS, 256, 256);

    // 10) window attention -> av [B,N,C]
    win_attn_kernel<<<B_SZ * HH, 256>>>(rel_bias);

    // 11) out = av @ proj_w + proj_b -> d_out segment 0
    gemmT(p_av, p_w + WOFF_PROJ, proj_b, nullptr, 0, 1.f, out0, ROWS, 256, 256);

    // 12) t_x = concat(out, depth, seg); t_k + t_v in ONE dual GEMM
    concat_kernel<<<(ROWS * TCC) / 256, 256>>>(out0, depth_t, seg_t);
    gemmT_dual(p_tx, p_w + WOFF_GK, gk_b, p_tk, p_w + WOFF_GV, gv_b, p_tv,
               ROWS, TCC, TCC);

    // 13) class-token attention (depth + seg) -> stacked g_dstok
    cls_attn_kernel<<<B_SZ * HH, 256>>>();

    // 14) final dth projection: one stacked GEMM [2*ROWS,64] @ [64,64] -> out1|out2
    gemm64(p_dstok, pdth_w, pdth_b, nullptr, 0, 1.f, out1, 2 * ROWS, 64, 64);
}